// round 11
// baseline (speedup 1.0000x reference)
#include <cuda_runtime.h>
#include <cuda_bf16.h>
#include <cstdint>

#define B_      64
#define L_      512
#define D_      768
#define NF_     100
#define WAIST_  768
#define KTOT    868     // D_ + NF_

#define BM      128
#define BN      128
#define KTILES  55      // ceil(880/16)
#define ESTR    104     // enrichment row stride (100 used, 100..103 zero)
#define NTILES_M 256    // B_ * (L_/BM)

#define ASZ     (128 * 12)   // A plane words per stage (stride 12: conflict-free)
#define BSZ     (8 * 136)    // B plane words per stage (stride 136)
#define STGW    (2 * ASZ + 2 * BSZ)   // 5248 words per stage

// ---------------------------------------------------------------------------
// Global scratch (allowed: __device__ globals)
// ---------------------------------------------------------------------------
__device__ int g_gidx[B_ * L_];
__device__ uint32_t g_Xhi[(size_t)NTILES_M * KTILES * 1024];  // [tile][kt][m][8]
__device__ uint32_t g_Xlo[(size_t)NTILES_M * KTILES * 1024];
__device__ uint32_t g_Whi[KTILES * 8 * WAIST_];               // [kt][j][n]
__device__ uint32_t g_Wlo[KTILES * 8 * WAIST_];

// ---------------------------------------------------------------------------
// helpers
// ---------------------------------------------------------------------------
__device__ __forceinline__ uint32_t pack_split(float f0, float f1, uint32_t& lo_out)
{
    __nv_bfloat16 h0 = __float2bfloat16(f0);
    __nv_bfloat16 h1 = __float2bfloat16(f1);
    __nv_bfloat16 l0 = __float2bfloat16(f0 - __bfloat162float(h0));
    __nv_bfloat16 l1 = __float2bfloat16(f1 - __bfloat162float(h1));
    __nv_bfloat162 hp; hp.x = h0; hp.y = h1;
    __nv_bfloat162 lp; lp.x = l0; lp.y = l1;
    lo_out = *reinterpret_cast<uint32_t*>(&lp);
    return *reinterpret_cast<uint32_t*>(&hp);
}

__device__ __forceinline__ void mma_bf16(float c[4], const uint32_t a[4],
                                         const uint32_t b[2])
{
    asm volatile(
        "mma.sync.aligned.m16n8k16.row.col.f32.bf16.bf16.f32 "
        "{%0,%1,%2,%3},{%4,%5,%6,%7},{%8,%9},{%0,%1,%2,%3};"
        : "+f"(c[0]), "+f"(c[1]), "+f"(c[2]), "+f"(c[3])
        : "r"(a[0]), "r"(a[1]), "r"(a[2]), "r"(a[3]), "r"(b[0]), "r"(b[1]));
}

__device__ __forceinline__ void cpa16(uint32_t dst_smem, const void* src)
{
    asm volatile("cp.async.cg.shared.global [%0], [%1], 16;\n"
                 :: "r"(dst_smem), "l"(src));
}

// ---------------------------------------------------------------------------
// Kernel 1: per-batch stream compaction index (ballot prefix-sum)
// ---------------------------------------------------------------------------
__global__ void compact_kernel(const int* __restrict__ valid)
{
    int b = blockIdx.x;
    int t = threadIdx.x;                 // 512 threads = L_
    int v = valid[b * L_ + t];
    g_gidx[b * L_ + t] = -1;

    __shared__ int warp_tot[16];
    unsigned mask = __ballot_sync(0xffffffffu, v != 0);
    int lane = t & 31, w = t >> 5;
    int intra = __popc(mask & ((1u << lane) - 1u));
    if (lane == 31) warp_tot[w] = __popc(mask);
    __syncthreads();
    int offset = 0;
    for (int i = 0; i < w; i++) offset += warp_tot[i];
    if (v) g_gidx[b * L_ + offset + intra] = t;
}

// ---------------------------------------------------------------------------
// Kernel 2: cls head  (64 x 768) @ (768 x 2)
// ---------------------------------------------------------------------------
__global__ void cls_kernel(const float* __restrict__ seq,
                           const float* __restrict__ cls_w,
                           const float* __restrict__ cls_b,
                           float* __restrict__ out)
{
    int b = blockIdx.x;
    int t = threadIdx.x;                 // 256
    const float* row = seq + (size_t)b * L_ * D_;   // l = 0
    float p0 = 0.f, p1 = 0.f;
    for (int d = t; d < D_; d += 256) {
        float x = row[d];
        p0 += x * cls_w[d * 2 + 0];
        p1 += x * cls_w[d * 2 + 1];
    }
    __shared__ float s0[256], s1[256];
    s0[t] = p0; s1[t] = p1;
    __syncthreads();
    for (int s = 128; s > 0; s >>= 1) {
        if (t < s) { s0[t] += s0[t + s]; s1[t] += s1[t + s]; }
        __syncthreads();
    }
    if (t == 0) {
        out[b * 2 + 0] = s0[0] + cls_b[0];
        out[b * 2 + 1] = s1[0] + cls_b[1];
    }
}

// ---------------------------------------------------------------------------
// Kernel 3: split w1 into k-pair-packed bf16x2 planes  g_Whi/g_Wlo[kt][j][n]
// ---------------------------------------------------------------------------
__global__ void prepw_kernel(const float* __restrict__ w1)
{
    int j  = blockIdx.x;     // 0..7
    int kt = blockIdx.y;     // 0..54
    int n  = threadIdx.x;    // 0..767
    int k  = kt * 16 + 2 * j;
    float f0 = (k     < KTOT) ? w1[(size_t)k * WAIST_ + n]       : 0.f;
    float f1 = (k + 1 < KTOT) ? w1[(size_t)(k + 1) * WAIST_ + n] : 0.f;
    uint32_t lo, hi = pack_split(f0, f1, lo);
    g_Whi[(kt * 8 + j) * WAIST_ + n] = hi;
    g_Wlo[(kt * 8 + j) * WAIST_ + n] = lo;
}

// ---------------------------------------------------------------------------
// Kernel 4: build X planes: gather + enrichment + split, GEMM-ready layout
//   g_Xhi[tile][kt][m][j]  (tile = b*4 + mblk, word = bf16x2(k0+2j, k0+2j+1))
// ---------------------------------------------------------------------------
__global__ __launch_bounds__(256, 2)
void prepx_kernel(const float* __restrict__ seq,
                  const float* __restrict__ feat,
                  const float* __restrict__ enr_w,
                  const float* __restrict__ enr_b)
{
    extern __shared__ float sm[];
    float* E  = sm;                   // BM*ESTR
    float* Fs = sm + BM * ESTR;       // BM*ESTR
    __shared__ int s_src[BM];

    int b    = blockIdx.y;
    int mblk = blockIdx.x;
    int m0   = mblk * BM;
    int tid  = threadIdx.x;

    if (tid < BM) s_src[tid] = g_gidx[b * L_ + m0 + tid];

    // enrichment tile E[128][104]
    for (int i = tid; i < BM * NF_; i += 256) {
        int m = i / NF_, c = i % NF_;
        Fs[m * ESTR + c] = feat[((size_t)(b * L_ + m0 + m)) * NF_ + c];
    }
    __syncthreads();
    for (int gg = tid; gg < 32 * ESTR; gg += 256) {
        int f  = gg % ESTR;
        int mq = gg / ESTR;
        float a0 = 0.f, a1 = 0.f, a2 = 0.f, a3 = 0.f;
        if (f < NF_) {
            float bb = __ldg(&enr_b[f]);
            a0 = bb; a1 = bb; a2 = bb; a3 = bb;
            const float* f0 = Fs + (mq * 4 + 0) * ESTR;
            const float* f1 = Fs + (mq * 4 + 1) * ESTR;
            const float* f2 = Fs + (mq * 4 + 2) * ESTR;
            const float* f3 = Fs + (mq * 4 + 3) * ESTR;
            #pragma unroll 4
            for (int k = 0; k < NF_; k++) {
                float w = __ldg(&enr_w[k * NF_ + f]);
                a0 += f0[k] * w; a1 += f1[k] * w;
                a2 += f2[k] * w; a3 += f3[k] * w;
            }
            a0 = fmaxf(a0, 0.f); a1 = fmaxf(a1, 0.f);
            a2 = fmaxf(a2, 0.f); a3 = fmaxf(a3, 0.f);
        }
        E[(mq * 4 + 0) * ESTR + f] = a0;
        E[(mq * 4 + 1) * ESTR + f] = a1;
        E[(mq * 4 + 2) * ESTR + f] = a2;
        E[(mq * 4 + 3) * ESTR + f] = a3;
    }
    __syncthreads();

    size_t tile = (size_t)(b * 4 + mblk);
    uint32_t* oh = g_Xhi + tile * KTILES * 1024;
    uint32_t* ol = g_Xlo + tile * KTILES * 1024;

    // seq region: kt 0..47
    for (int kt = 0; kt < 48; kt++) {
        int k0 = kt * 16;
        for (int idx = tid; idx < 1024; idx += 256) {
            int m = idx >> 3, j = idx & 7;
            int s = s_src[m];
            float f0 = 0.f, f1 = 0.f;
            if (s >= 0) {
                float2 v = *(const float2*)(seq + ((size_t)(b * L_ + s)) * D_ + k0 + 2 * j);
                f0 = v.x; f1 = v.y;
            }
            uint32_t lo, hi = pack_split(f0, f1, lo);
            oh[kt * 1024 + idx] = hi;
            ol[kt * 1024 + idx] = lo;
        }
    }
    // enriched region: kt 48..54
    for (int kt = 48; kt < KTILES; kt++) {
        int k0 = kt * 16;
        for (int idx = tid; idx < 1024; idx += 256) {
            int m = idx >> 3, j = idx & 7;
            int col0 = k0 + 2 * j - D_;         // even, 0..110
            float f0 = 0.f, f1 = 0.f;
            if (col0 < ESTR) {
                float2 v = *(const float2*)(E + m * ESTR + col0);
                f0 = v.x; f1 = v.y;
            }
            uint32_t lo, hi = pack_split(f0, f1, lo);
            oh[kt * 1024 + idx] = hi;
            ol[kt * 1024 + idx] = lo;
        }
    }
}

// ---------------------------------------------------------------------------
// Kernel 5: main GEMM (3-term bf16 mma, cp.async double-buffered) + tag head
// Warp grid 2x4: warp (wy,wx) owns rows wy*64..+64, cols wx*32..+32.
// ---------------------------------------------------------------------------
__global__ __launch_bounds__(256, 2)
void gemm_kernel(const float* __restrict__ b1,
                 const float* __restrict__ w2,
                 const float* __restrict__ b2,
                 float* __restrict__ out)
{
    extern __shared__ uint32_t smw[];            // 2 stages x STGW words
    __shared__ float s_tagp[4][BM][3];

    int b    = blockIdx.y;
    int mblk = blockIdx.x;
    int m0   = mblk * BM;
    int tile = b * 4 + mblk;
    int tid  = threadIdx.x;
    int warp = tid >> 5, lane = tid & 31;
    int wy = warp >> 2, wx = warp & 3;
    int g  = lane >> 2, t4 = lane & 3;

    for (int i = tid; i < 4 * BM * 3; i += 256)
        (&s_tagp[0][0][0])[i] = 0.f;

    const uint32_t* XH = g_Xhi + (size_t)tile * KTILES * 1024;
    const uint32_t* XL = g_Xlo + (size_t)tile * KTILES * 1024;

    uint32_t smem_base = (uint32_t)__cvta_generic_to_shared(smw);
    // per-thread copy geometry
    int mA = tid >> 1, cA = tid & 1;             // A: 2 chunks per row m
    uint32_t dA = (uint32_t)(mA * 12 + cA * 4);  // word offset in A plane
    int jB = tid >> 5, cB = tid & 31;            // B: 32 chunks per row j
    uint32_t dB = (uint32_t)(jB * 136 + cB * 4);

    #define PREFETCH(ktv, stg, n0v) do {                                        \
        uint32_t sb = smem_base + (uint32_t)(stg) * STGW * 4;                   \
        cpa16(sb + dA * 4,             XH + (ktv) * 1024 + tid * 4);            \
        cpa16(sb + (ASZ + dA) * 4,     XL + (ktv) * 1024 + tid * 4);            \
        cpa16(sb + (2 * ASZ + dB) * 4, g_Whi + ((ktv) * 8 + jB) * WAIST_ + (n0v) + cB * 4); \
        cpa16(sb + (2 * ASZ + BSZ + dB) * 4, g_Wlo + ((ktv) * 8 + jB) * WAIST_ + (n0v) + cB * 4); \
        asm volatile("cp.async.commit_group;\n" ::: "memory");                  \
    } while (0)

    for (int nt = 0; nt < WAIST_ / BN; nt++) {
        int n0 = nt * BN;
        float acc[4][4][4];
        #pragma unroll
        for (int mt = 0; mt < 4; mt++)
            #pragma unroll
            for (int nn = 0; nn < 4; nn++)
                #pragma unroll
                for (int q = 0; q < 4; q++) acc[mt][nn][q] = 0.f;

        PREFETCH(0, 0, n0);

        for (int kt = 0; kt < KTILES; kt++) {
            int cur = kt & 1;
            if (kt < KTILES - 1) {
                PREFETCH(kt + 1, cur ^ 1, n0);
                asm volatile("cp.async.wait_group 1;\n" ::: "memory");
            } else {
                asm volatile("cp.async.wait_group 0;\n" ::: "memory");
            }
            __syncthreads();

            uint32_t* as_hi = smw + cur * STGW;
            uint32_t* as_lo = as_hi + ASZ;
            uint32_t* bs_hi = as_lo + ASZ;
            uint32_t* bs_lo = bs_hi + BSZ;

            uint32_t Bh[4][2], Bl[4][2];
            #pragma unroll
            for (int nn = 0; nn < 4; nn++) {
                int nb = wx * 32 + nn * 8 + g;
                Bh[nn][0] = bs_hi[t4 * 136 + nb];
                Bh[nn][1] = bs_hi[(t4 + 4) * 136 + nb];
                Bl[nn][0] = bs_lo[t4 * 136 + nb];
                Bl[nn][1] = bs_lo[(t4 + 4) * 136 + nb];
            }
            #pragma unroll
            for (int mt = 0; mt < 4; mt++) {
                int rm = wy * 64 + mt * 16 + g;
                uint32_t Ah[4], Al[4];
                Ah[0] = as_hi[rm * 12 + t4];
                Ah[1] = as_hi[(rm + 8) * 12 + t4];
                Ah[2] = as_hi[rm * 12 + t4 + 4];
                Ah[3] = as_hi[(rm + 8) * 12 + t4 + 4];
                Al[0] = as_lo[rm * 12 + t4];
                Al[1] = as_lo[(rm + 8) * 12 + t4];
                Al[2] = as_lo[rm * 12 + t4 + 4];
                Al[3] = as_lo[(rm + 8) * 12 + t4 + 4];
                #pragma unroll
                for (int nn = 0; nn < 4; nn++) {
                    mma_bf16(acc[mt][nn], Ah, Bl[nn]);   // small terms first
                    mma_bf16(acc[mt][nn], Al, Bh[nn]);
                    mma_bf16(acc[mt][nn], Ah, Bh[nn]);
                }
            }
            __syncthreads();
        }

        // epilogue: bias + relu + tag-head partials
        #pragma unroll
        for (int mt = 0; mt < 4; mt++) {
            float tg0[3] = {0.f, 0.f, 0.f};
            float tg1[3] = {0.f, 0.f, 0.f};
            #pragma unroll
            for (int nn = 0; nn < 4; nn++) {
                #pragma unroll
                for (int cc = 0; cc < 2; cc++) {
                    int n = n0 + wx * 32 + nn * 8 + 2 * t4 + cc;
                    float bias = __ldg(&b1[n]);
                    float w20 = __ldg(&w2[n * 3 + 0]);
                    float w21 = __ldg(&w2[n * 3 + 1]);
                    float w22 = __ldg(&w2[n * 3 + 2]);
                    float h0 = fmaxf(acc[mt][nn][cc]     + bias, 0.f);
                    float h1 = fmaxf(acc[mt][nn][cc + 2] + bias, 0.f);
                    tg0[0] += h0 * w20; tg0[1] += h0 * w21; tg0[2] += h0 * w22;
                    tg1[0] += h1 * w20; tg1[1] += h1 * w21; tg1[2] += h1 * w22;
                }
            }
            #pragma unroll
            for (int t3 = 0; t3 < 3; t3++) {
                tg0[t3] += __shfl_xor_sync(0xffffffffu, tg0[t3], 1);
                tg0[t3] += __shfl_xor_sync(0xffffffffu, tg0[t3], 2);
                tg1[t3] += __shfl_xor_sync(0xffffffffu, tg1[t3], 1);
                tg1[t3] += __shfl_xor_sync(0xffffffffu, tg1[t3], 2);
            }
            if (t4 == 0) {
                int r0 = wy * 64 + mt * 16 + g;
                #pragma unroll
                for (int t3 = 0; t3 < 3; t3++) {
                    s_tagp[wx][r0][t3]     += tg0[t3];
                    s_tagp[wx][r0 + 8][t3] += tg1[t3];
                }
            }
        }
        __syncthreads();   // s_tagp writes done before next nt / final read
    }

    // tag_logits at out + 128; fixed-order wx sum (deterministic)
    for (int i = tid; i < BM * 3; i += 256) {
        int m = i / 3, t = i % 3;
        float v = s_tagp[0][m][t] + s_tagp[1][m][t]
                + s_tagp[2][m][t] + s_tagp[3][m][t];
        out[128 + ((size_t)(b * L_ + m0 + m)) * 3 + t] = v + __ldg(&b2[t]);
    }
    #undef PREFETCH
}

// ---------------------------------------------------------------------------
extern "C" void kernel_launch(void* const* d_in, const int* in_sizes, int n_in,
                              void* d_out, int out_size)
{
    const float* seq   = (const float*)d_in[0];
    const float* feat  = (const float*)d_in[1];
    const int*   valid = (const int*)  d_in[2];
    const float* enr_w = (const float*)d_in[3];
    const float* enr_b = (const float*)d_in[4];
    const float* w1    = (const float*)d_in[5];
    const float* b1    = (const float*)d_in[6];
    const float* w2    = (const float*)d_in[7];
    const float* b2    = (const float*)d_in[8];
    const float* cls_w = (const float*)d_in[9];
    const float* cls_b = (const float*)d_in[10];
    float* out = (float*)d_out;

    const int smem_prep = 2 * BM * ESTR * (int)sizeof(float);   // 106,496 B
    const int smem_gemm = 2 * STGW * (int)sizeof(uint32_t);     // 41,984 B
    cudaFuncSetAttribute(prepx_kernel, cudaFuncAttributeMaxDynamicSharedMemorySize, smem_prep);

    compact_kernel<<<B_, L_>>>(valid);
    prepw_kernel<<<dim3(8, KTILES), WAIST_>>>(w1);
    prepx_kernel<<<dim3(4, B_), 256, smem_prep>>>(seq, feat, enr_w, enr_b);
    gemm_kernel<<<dim3(4, B_), 256, smem_gemm>>>(b1, w2, b2, out);
    cls_kernel<<<B_, 256>>>(seq, cls_w, cls_b, out);
}

// round 15
// speedup vs baseline: 1.4953x; 1.4953x over previous
#include <cuda_runtime.h>
#include <cuda_bf16.h>
#include <cstdint>

#define B_      64
#define L_      512
#define D_      768
#define NF_     100
#define WAIST_  768
#define KTOT    868
#define ESTR    104
#define KTILES  55            // ceil(880/16)
#define KSKIP   48            // seq-region k-tiles (768/16)
#define NNT     6

#define ASZ     (128 * 12)    // A plane words per stage (stride 12, words 0..7 used)
#define BSZ     (8 * 136)     // B plane words per stage
#define STGW    (2 * ASZ + 2 * BSZ)   // 5248 words per stage
#define NSTG    3

// ---------------------------------------------------------------------------
// Global scratch (__device__ globals only)
// ---------------------------------------------------------------------------
__device__ int g_gidx[B_ * L_];
__device__ int g_nvalid[B_];
__device__ uint32_t g_Xhi[(size_t)256 * KTILES * 1024];  // [tile][kt][m][8]
__device__ uint32_t g_Xlo[(size_t)256 * KTILES * 1024];
__device__ uint32_t g_Whi[KTILES * 8 * WAIST_];          // [kt][j][n]
__device__ uint32_t g_Wlo[KTILES * 8 * WAIST_];
__device__ float    g_tagp[256 * NNT * 384];             // per-(tile,nt) tag partials

// ---------------------------------------------------------------------------
// helpers
// ---------------------------------------------------------------------------
__device__ __forceinline__ uint32_t pack_split(float f0, float f1, uint32_t& lo_out)
{
    __nv_bfloat16 h0 = __float2bfloat16(f0);
    __nv_bfloat16 h1 = __float2bfloat16(f1);
    __nv_bfloat16 l0 = __float2bfloat16(f0 - __bfloat162float(h0));
    __nv_bfloat16 l1 = __float2bfloat16(f1 - __bfloat162float(h1));
    __nv_bfloat162 hp; hp.x = h0; hp.y = h1;
    __nv_bfloat162 lp; lp.x = l0; lp.y = l1;
    lo_out = *reinterpret_cast<uint32_t*>(&lp);
    return *reinterpret_cast<uint32_t*>(&hp);
}

__device__ __forceinline__ void mma_bf16(float c[4], const uint32_t a[4],
                                         const uint32_t b[2])
{
    asm volatile(
        "mma.sync.aligned.m16n8k16.row.col.f32.bf16.bf16.f32 "
        "{%0,%1,%2,%3},{%4,%5,%6,%7},{%8,%9},{%0,%1,%2,%3};"
        : "+f"(c[0]), "+f"(c[1]), "+f"(c[2]), "+f"(c[3])
        : "r"(a[0]), "r"(a[1]), "r"(a[2]), "r"(a[3]), "r"(b[0]), "r"(b[1]));
}

__device__ __forceinline__ void cpa16(uint32_t dst_smem, const void* src)
{
    asm volatile("cp.async.cg.shared.global [%0], [%1], 16;\n"
                 :: "r"(dst_smem), "l"(src));
}

// ---------------------------------------------------------------------------
// Kernel 1: compaction index + per-batch valid count
// ---------------------------------------------------------------------------
__global__ void compact_kernel(const int* __restrict__ valid)
{
    int b = blockIdx.x;
    int t = threadIdx.x;                 // 512
    int v = valid[b * L_ + t];
    g_gidx[b * L_ + t] = -1;

    __shared__ int warp_tot[16];
    unsigned mask = __ballot_sync(0xffffffffu, v != 0);
    int lane = t & 31, w = t >> 5;
    int intra = __popc(mask & ((1u << lane) - 1u));
    if (lane == 31) warp_tot[w] = __popc(mask);
    __syncthreads();
    int offset = 0;
    for (int i = 0; i < w; i++) offset += warp_tot[i];
    if (v) g_gidx[b * L_ + offset + intra] = t;
    if (t == L_ - 1) g_nvalid[b] = offset + __popc(mask);
}

// ---------------------------------------------------------------------------
// Kernel 2: cls head
// ---------------------------------------------------------------------------
__global__ void cls_kernel(const float* __restrict__ seq,
                           const float* __restrict__ cls_w,
                           const float* __restrict__ cls_b,
                           float* __restrict__ out)
{
    int b = blockIdx.x;
    int t = threadIdx.x;                 // 256
    const float* row = seq + (size_t)b * L_ * D_;
    float p0 = 0.f, p1 = 0.f;
    for (int d = t; d < D_; d += 256) {
        float x = row[d];
        p0 += x * cls_w[d * 2 + 0];
        p1 += x * cls_w[d * 2 + 1];
    }
    __shared__ float s0[256], s1[256];
    s0[t] = p0; s1[t] = p1;
    __syncthreads();
    for (int s = 128; s > 0; s >>= 1) {
        if (t < s) { s0[t] += s0[t + s]; s1[t] += s1[t + s]; }
        __syncthreads();
    }
    if (t == 0) {
        out[b * 2 + 0] = s0[0] + cls_b[0];
        out[b * 2 + 1] = s1[0] + cls_b[1];
    }
}

// ---------------------------------------------------------------------------
// Kernel 3: split w1 -> g_Whi/g_Wlo[kt][j][n]
// ---------------------------------------------------------------------------
__global__ void prepw_kernel(const float* __restrict__ w1)
{
    int j  = blockIdx.x;     // 0..7
    int kt = blockIdx.y;     // 0..54
    int n  = threadIdx.x;    // 0..767
    int k  = kt * 16 + 2 * j;
    float f0 = (k     < KTOT) ? w1[(size_t)k * WAIST_ + n]       : 0.f;
    float f1 = (k + 1 < KTOT) ? w1[(size_t)(k + 1) * WAIST_ + n] : 0.f;
    uint32_t lo, hi = pack_split(f0, f1, lo);
    g_Whi[(kt * 8 + j) * WAIST_ + n] = hi;
    g_Wlo[(kt * 8 + j) * WAIST_ + n] = lo;
}

// ---------------------------------------------------------------------------
// Kernel 4: X planes (gather + enrichment + split); skips all-zero seq chunks
// ---------------------------------------------------------------------------
__global__ __launch_bounds__(256, 2)
void prepx_kernel(const float* __restrict__ seq,
                  const float* __restrict__ feat,
                  const float* __restrict__ enr_w,
                  const float* __restrict__ enr_b)
{
    extern __shared__ float sm[];
    float* E  = sm;                   // 128*ESTR
    float* Fs = sm + 128 * ESTR;
    __shared__ int s_src[128];

    int b    = blockIdx.y;
    int mblk = blockIdx.x;
    int m0   = mblk * 128;
    int tid  = threadIdx.x;

    if (tid < 128) s_src[tid] = g_gidx[b * L_ + m0 + tid];

    for (int i = tid; i < 128 * NF_; i += 256) {
        int m = i / NF_, c = i % NF_;
        Fs[m * ESTR + c] = feat[((size_t)(b * L_ + m0 + m)) * NF_ + c];
    }
    __syncthreads();
    for (int gg = tid; gg < 32 * ESTR; gg += 256) {
        int f  = gg % ESTR;
        int mq = gg / ESTR;
        float a0 = 0.f, a1 = 0.f, a2 = 0.f, a3 = 0.f;
        if (f < NF_) {
            float bb = __ldg(&enr_b[f]);
            a0 = bb; a1 = bb; a2 = bb; a3 = bb;
            const float* f0 = Fs + (mq * 4 + 0) * ESTR;
            const float* f1 = Fs + (mq * 4 + 1) * ESTR;
            const float* f2 = Fs + (mq * 4 + 2) * ESTR;
            const float* f3 = Fs + (mq * 4 + 3) * ESTR;
            #pragma unroll 4
            for (int k = 0; k < NF_; k++) {
                float w = __ldg(&enr_w[k * NF_ + f]);
                a0 += f0[k] * w; a1 += f1[k] * w;
                a2 += f2[k] * w; a3 += f3[k] * w;
            }
            a0 = fmaxf(a0, 0.f); a1 = fmaxf(a1, 0.f);
            a2 = fmaxf(a2, 0.f); a3 = fmaxf(a3, 0.f);
        }
        E[(mq * 4 + 0) * ESTR + f] = a0;
        E[(mq * 4 + 1) * ESTR + f] = a1;
        E[(mq * 4 + 2) * ESTR + f] = a2;
        E[(mq * 4 + 3) * ESTR + f] = a3;
    }
    __syncthreads();

    size_t tile = (size_t)(b * 4 + mblk);
    uint32_t* oh = g_Xhi + tile * KTILES * 1024;
    uint32_t* ol = g_Xlo + tile * KTILES * 1024;
    bool skip = (m0 >= g_nvalid[b]);     // whole tile zero in seq region

    if (!skip) {
        // seq region, coalesced float4: 128 rows x 192 float4
        for (int idx = tid; idx < 128 * 192; idx += 256) {
            int m = idx / 192, f4 = idx % 192;
            int s = s_src[m];
            float4 v = make_float4(0.f, 0.f, 0.f, 0.f);
            if (s >= 0)
                v = *(const float4*)(seq + ((size_t)(b * L_ + s)) * D_ + f4 * 4);
            int kt = f4 >> 2, jj = (f4 & 3) * 2;
            uint32_t lo0, hi0 = pack_split(v.x, v.y, lo0);
            uint32_t lo1, hi1 = pack_split(v.z, v.w, lo1);
            int base = kt * 1024 + m * 8 + jj;
            oh[base] = hi0; oh[base + 1] = hi1;
            ol[base] = lo0; ol[base + 1] = lo1;
        }
    }
    // enrichment region: kt 48..54, 128 rows x 28 float4 (cols 0..111, >=104 zero)
    for (int idx = tid; idx < 128 * 28; idx += 256) {
        int m = idx / 28, f4 = idx % 28;
        int col = f4 * 4;                 // 0..108
        float4 v = make_float4(0.f, 0.f, 0.f, 0.f);
        if (col < ESTR)                   // col<=100 -> col+3<=103 in-bounds (zero-padded)
            v = *(const float4*)(E + m * ESTR + col);
        int kt = 48 + (col >> 4);
        int jj = (col & 15) >> 1;
        uint32_t lo0, hi0 = pack_split(v.x, v.y, lo0);
        uint32_t lo1, hi1 = pack_split(v.z, v.w, lo1);
        int base = kt * 1024 + m * 8 + jj;
        oh[base] = hi0; oh[base + 1] = hi1;
        ol[base] = lo0; ol[base + 1] = lo1;
    }
}

// ---------------------------------------------------------------------------
// Kernel 5: GEMM, one CTA per (tile, nt). 3-stage cp.async, 1 sync/k-tile.
// Warp grid 2x4: warp (wy,wx) owns rows wy*64..+64, cols wx*32..+32.
// ---------------------------------------------------------------------------
__global__ __launch_bounds__(256, 2)
void gemm_kernel(const float* __restrict__ b1,
                 const float* __restrict__ w2)
{
    extern __shared__ uint32_t smw[];            // NSTG x STGW words
    __shared__ float s_tagp[4][128][3];

    int nt   = blockIdx.x;                       // 0..5
    int tile = blockIdx.y;                       // 0..255
    int b    = tile >> 2, mblk = tile & 3;
    int n0   = nt * 128;
    int tid  = threadIdx.x;
    int warp = tid >> 5, lane = tid & 31;
    int wy = warp >> 2, wx = warp & 3;
    int g  = lane >> 2, t4 = lane & 3;

    int kstart = (mblk * 128 >= g_nvalid[b]) ? KSKIP : 0;
    int nkt    = KTILES - kstart;                // 55 or 7

    for (int i = tid; i < 4 * 128 * 3; i += 256)
        (&s_tagp[0][0][0])[i] = 0.f;

    const uint32_t* XH = g_Xhi + (size_t)tile * KTILES * 1024;
    const uint32_t* XL = g_Xlo + (size_t)tile * KTILES * 1024;

    uint32_t smem_base = (uint32_t)__cvta_generic_to_shared(smw);
    int mA = tid >> 1, cA = tid & 1;
    uint32_t dA = (uint32_t)(mA * 12 + cA * 4);
    int jB = tid >> 5, cB = tid & 31;
    uint32_t dB = (uint32_t)(jB * 136 + cB * 4);

    #define FILL(iv) do {                                                       \
        int _kt = kstart + (iv);                                                \
        uint32_t sb = smem_base + (uint32_t)(((iv) % NSTG) * STGW) * 4;         \
        cpa16(sb + dA * 4,             XH + _kt * 1024 + tid * 4);              \
        cpa16(sb + (ASZ + dA) * 4,     XL + _kt * 1024 + tid * 4);              \
        cpa16(sb + (2 * ASZ + dB) * 4, g_Whi + (_kt * 8 + jB) * WAIST_ + n0 + cB * 4); \
        cpa16(sb + (2 * ASZ + BSZ + dB) * 4, g_Wlo + (_kt * 8 + jB) * WAIST_ + n0 + cB * 4); \
        asm volatile("cp.async.commit_group;\n" ::: "memory");                  \
    } while (0)

    float acc[4][4][4];
    #pragma unroll
    for (int mt = 0; mt < 4; mt++)
        #pragma unroll
        for (int nn = 0; nn < 4; nn++)
            #pragma unroll
            for (int q = 0; q < 4; q++) acc[mt][nn][q] = 0.f;

    FILL(0); FILL(1);

    for (int i = 0; i < nkt; i++) {
        if (i == nkt - 1)
            asm volatile("cp.async.wait_group 0;\n" ::: "memory");
        else
            asm volatile("cp.async.wait_group 1;\n" ::: "memory");
        __syncthreads();                 // stage i ready; stage i-1 reads done
        if (i + 2 < nkt) FILL(i + 2);    // rewrites stage (i-1)%3 — safe post-sync

        uint32_t* as_hi = smw + (i % NSTG) * STGW;
        uint32_t* as_lo = as_hi + ASZ;
        uint32_t* bs_hi = as_lo + ASZ;
        uint32_t* bs_lo = bs_hi + BSZ;

        uint32_t Bh[4][2], Bl[4][2];
        #pragma unroll
        for (int nn = 0; nn < 4; nn++) {
            int nb = wx * 32 + nn * 8 + g;
            Bh[nn][0] = bs_hi[t4 * 136 + nb];
            Bh[nn][1] = bs_hi[(t4 + 4) * 136 + nb];
            Bl[nn][0] = bs_lo[t4 * 136 + nb];
            Bl[nn][1] = bs_lo[(t4 + 4) * 136 + nb];
        }
        #pragma unroll
        for (int mt = 0; mt < 4; mt++) {
            int rm = wy * 64 + mt * 16 + g;
            uint32_t Ah[4], Al[4];
            Ah[0] = as_hi[rm * 12 + t4];
            Ah[1] = as_hi[(rm + 8) * 12 + t4];
            Ah[2] = as_hi[rm * 12 + t4 + 4];
            Ah[3] = as_hi[(rm + 8) * 12 + t4 + 4];
            Al[0] = as_lo[rm * 12 + t4];
            Al[1] = as_lo[(rm + 8) * 12 + t4];
            Al[2] = as_lo[rm * 12 + t4 + 4];
            Al[3] = as_lo[(rm + 8) * 12 + t4 + 4];
            #pragma unroll
            for (int nn = 0; nn < 4; nn++) {
                mma_bf16(acc[mt][nn], Ah, Bl[nn]);   // small terms first
                mma_bf16(acc[mt][nn], Al, Bh[nn]);
                mma_bf16(acc[mt][nn], Ah, Bh[nn]);
            }
        }
    }

    // epilogue: bias + relu + tag partials for this nt
    #pragma unroll
    for (int mt = 0; mt < 4; mt++) {
        float tg0[3] = {0.f, 0.f, 0.f};
        float tg1[3] = {0.f, 0.f, 0.f};
        #pragma unroll
        for (int nn = 0; nn < 4; nn++) {
            #pragma unroll
            for (int cc = 0; cc < 2; cc++) {
                int n = n0 + wx * 32 + nn * 8 + 2 * t4 + cc;
                float bias = __ldg(&b1[n]);
                float w20 = __ldg(&w2[n * 3 + 0]);
                float w21 = __ldg(&w2[n * 3 + 1]);
                float w22 = __ldg(&w2[n * 3 + 2]);
                float h0 = fmaxf(acc[mt][nn][cc]     + bias, 0.f);
                float h1 = fmaxf(acc[mt][nn][cc + 2] + bias, 0.f);
                tg0[0] += h0 * w20; tg0[1] += h0 * w21; tg0[2] += h0 * w22;
                tg1[0] += h1 * w20; tg1[1] += h1 * w21; tg1[2] += h1 * w22;
            }
        }
        #pragma unroll
        for (int t3 = 0; t3 < 3; t3++) {
            tg0[t3] += __shfl_xor_sync(0xffffffffu, tg0[t3], 1);
            tg0[t3] += __shfl_xor_sync(0xffffffffu, tg0[t3], 2);
            tg1[t3] += __shfl_xor_sync(0xffffffffu, tg1[t3], 1);
            tg1[t3] += __shfl_xor_sync(0xffffffffu, tg1[t3], 2);
        }
        if (t4 == 0) {
            int r0 = wy * 64 + mt * 16 + g;
            #pragma unroll
            for (int t3 = 0; t3 < 3; t3++) {
                s_tagp[wx][r0][t3]     = tg0[t3];
                s_tagp[wx][r0 + 8][t3] = tg1[t3];
            }
        }
    }
    __syncthreads();
    // fixed-order wx sum -> global partials for (tile, nt)
    float* dst = g_tagp + (size_t)(tile * NNT + nt) * 384;
    for (int i = tid; i < 384; i += 256) {
        int m = i / 3, t = i % 3;
        dst[i] = s_tagp[0][m][t] + s_tagp[1][m][t]
               + s_tagp[2][m][t] + s_tagp[3][m][t];
    }
    #undef FILL
}

// ---------------------------------------------------------------------------
// Kernel 6: sum nt partials (fixed order) + b2 -> tag_logits
// ---------------------------------------------------------------------------
__global__ void tagred_kernel(const float* __restrict__ b2,
                              float* __restrict__ out)
{
    int tile = blockIdx.x;
    int i = threadIdx.x;                 // 384
    int b = tile >> 2, mblk = tile & 3;
    int m = i / 3, t = i % 3;
    float v = __ldg(&b2[t]);
    #pragma unroll
    for (int nt = 0; nt < NNT; nt++)
        v += g_tagp[(size_t)(tile * NNT + nt) * 384 + i];
    out[128 + ((size_t)(b * L_ + mblk * 128 + m)) * 3 + t] = v;
}

// ---------------------------------------------------------------------------
extern "C" void kernel_launch(void* const* d_in, const int* in_sizes, int n_in,
                              void* d_out, int out_size)
{
    const float* seq   = (const float*)d_in[0];
    const float* feat  = (const float*)d_in[1];
    const int*   valid = (const int*)  d_in[2];
    const float* enr_w = (const float*)d_in[3];
    const float* enr_b = (const float*)d_in[4];
    const float* w1    = (const float*)d_in[5];
    const float* b1    = (const float*)d_in[6];
    const float* w2    = (const float*)d_in[7];
    const float* b2    = (const float*)d_in[8];
    const float* cls_w = (const float*)d_in[9];
    const float* cls_b = (const float*)d_in[10];
    float* out = (float*)d_out;

    const int smem_prep = 2 * 128 * ESTR * (int)sizeof(float);   // 106,496 B
    const int smem_gemm = NSTG * STGW * (int)sizeof(uint32_t);   // 62,976 B
    cudaFuncSetAttribute(prepx_kernel, cudaFuncAttributeMaxDynamicSharedMemorySize, smem_prep);
    cudaFuncSetAttribute(gemm_kernel,  cudaFuncAttributeMaxDynamicSharedMemorySize, smem_gemm);

    compact_kernel<<<B_, L_>>>(valid);
    prepw_kernel<<<dim3(8, KTILES), WAIST_>>>(w1);
    prepx_kernel<<<dim3(4, B_), 256, smem_prep>>>(seq, feat, enr_w, enr_b);
    gemm_kernel<<<dim3(NNT, 256), 256, smem_gemm>>>(b1, w2);
    tagred_kernel<<<256, 384>>>(b2, out);
    cls_kernel<<<B_, 256>>>(seq, cls_w, cls_b, out);
}

// round 16
// speedup vs baseline: 1.6803x; 1.1237x over previous
#include <cuda_runtime.h>
#include <cuda_bf16.h>
#include <cstdint>

#define B_      64
#define L_      512
#define D_      768
#define NF_     100
#define WAIST_  768
#define KTOT    868
#define ESTR    104
#define KTILES  56            // K padded to 896 with zeros
#define KSKIP   48            // seq-region k-tiles (768/16)
#define NNT     6

#define NSTG    3
#define STGB    32768         // bytes per stage: 2 k-tiles x (Ahi,Alo,Bhi,Blo) x 4KB
#define STGWRD  8192          // words per stage

// ---------------------------------------------------------------------------
// Global scratch (__device__ globals only)
// ---------------------------------------------------------------------------
__device__ int g_gidx[B_ * L_];
__device__ int g_nvalid[B_];
__device__ uint32_t g_Xhi[(size_t)256 * KTILES * 1024];  // [tile][kt][m][8] (perm j)
__device__ uint32_t g_Xlo[(size_t)256 * KTILES * 1024];
__device__ uint32_t g_Whi[KTILES * WAIST_ * 8];          // [kt][n][8] (perm j)
__device__ uint32_t g_Wlo[KTILES * WAIST_ * 8];
__device__ float    g_tagp[256 * NNT * 384];             // per-(tile,nt) tag partials

// ---------------------------------------------------------------------------
// helpers
// ---------------------------------------------------------------------------
__device__ __forceinline__ int permf(int j) { return (j & 3) * 2 + (j >> 2); }

__device__ __forceinline__ uint32_t pack_split(float f0, float f1, uint32_t& lo_out)
{
    __nv_bfloat16 h0 = __float2bfloat16(f0);
    __nv_bfloat16 h1 = __float2bfloat16(f1);
    __nv_bfloat16 l0 = __float2bfloat16(f0 - __bfloat162float(h0));
    __nv_bfloat16 l1 = __float2bfloat16(f1 - __bfloat162float(h1));
    __nv_bfloat162 hp; hp.x = h0; hp.y = h1;
    __nv_bfloat162 lp; lp.x = l0; lp.y = l1;
    lo_out = *reinterpret_cast<uint32_t*>(&lp);
    return *reinterpret_cast<uint32_t*>(&hp);
}

__device__ __forceinline__ void mma_bf16(float c[4], const uint32_t a[4],
                                         const uint32_t b[2])
{
    asm volatile(
        "mma.sync.aligned.m16n8k16.row.col.f32.bf16.bf16.f32 "
        "{%0,%1,%2,%3},{%4,%5,%6,%7},{%8,%9},{%0,%1,%2,%3};"
        : "+f"(c[0]), "+f"(c[1]), "+f"(c[2]), "+f"(c[3])
        : "r"(a[0]), "r"(a[1]), "r"(a[2]), "r"(a[3]), "r"(b[0]), "r"(b[1]));
}

__device__ __forceinline__ void cpa16(uint32_t dst_smem, const void* src)
{
    asm volatile("cp.async.cg.shared.global [%0], [%1], 16;\n"
                 :: "r"(dst_smem), "l"(src));
}

// ---------------------------------------------------------------------------
// Kernel 1: compaction index + per-batch valid count
// ---------------------------------------------------------------------------
__global__ void compact_kernel(const int* __restrict__ valid)
{
    int b = blockIdx.x;
    int t = threadIdx.x;                 // 512
    int v = valid[b * L_ + t];
    g_gidx[b * L_ + t] = -1;

    __shared__ int warp_tot[16];
    unsigned mask = __ballot_sync(0xffffffffu, v != 0);
    int lane = t & 31, w = t >> 5;
    int intra = __popc(mask & ((1u << lane) - 1u));
    if (lane == 31) warp_tot[w] = __popc(mask);
    __syncthreads();
    int offset = 0;
    for (int i = 0; i < w; i++) offset += warp_tot[i];
    if (v) g_gidx[b * L_ + offset + intra] = t;
    if (t == L_ - 1) g_nvalid[b] = offset + __popc(mask);
}

// ---------------------------------------------------------------------------
// Kernel 2: cls head
// ---------------------------------------------------------------------------
__global__ void cls_kernel(const float* __restrict__ seq,
                           const float* __restrict__ cls_w,
                           const float* __restrict__ cls_b,
                           float* __restrict__ out)
{
    int b = blockIdx.x;
    int t = threadIdx.x;                 // 256
    const float* row = seq + (size_t)b * L_ * D_;
    float p0 = 0.f, p1 = 0.f;
    for (int d = t; d < D_; d += 256) {
        float x = row[d];
        p0 += x * cls_w[d * 2 + 0];
        p1 += x * cls_w[d * 2 + 1];
    }
    __shared__ float s0[256], s1[256];
    s0[t] = p0; s1[t] = p1;
    __syncthreads();
    for (int s = 128; s > 0; s >>= 1) {
        if (t < s) { s0[t] += s0[t + s]; s1[t] += s1[t + s]; }
        __syncthreads();
    }
    if (t == 0) {
        out[b * 2 + 0] = s0[0] + cls_b[0];
        out[b * 2 + 1] = s1[0] + cls_b[1];
    }
}

// ---------------------------------------------------------------------------
// Kernel 3: split w1 -> g_Whi/g_Wlo[kt][n][perm(j)]
// ---------------------------------------------------------------------------
__global__ void prepw_kernel(const float* __restrict__ w1)
{
    int j  = blockIdx.x;     // 0..7
    int kt = blockIdx.y;     // 0..55
    int n  = threadIdx.x;    // 0..767
    int k  = kt * 16 + 2 * j;
    float f0 = (k     < KTOT) ? w1[(size_t)k * WAIST_ + n]       : 0.f;
    float f1 = (k + 1 < KTOT) ? w1[(size_t)(k + 1) * WAIST_ + n] : 0.f;
    uint32_t lo, hi = pack_split(f0, f1, lo);
    int idx = (kt * WAIST_ + n) * 8 + permf(j);
    g_Whi[idx] = hi;
    g_Wlo[idx] = lo;
}

// ---------------------------------------------------------------------------
// Kernel 4: X planes (gather + enrichment + split); skips all-zero seq chunks
// ---------------------------------------------------------------------------
__global__ __launch_bounds__(256, 2)
void prepx_kernel(const float* __restrict__ seq,
                  const float* __restrict__ feat,
                  const float* __restrict__ enr_w,
                  const float* __restrict__ enr_b)
{
    extern __shared__ float sm[];
    float* E  = sm;                   // 128*ESTR
    float* Fs = sm + 128 * ESTR;
    __shared__ int s_src[128];

    int b    = blockIdx.y;
    int mblk = blockIdx.x;
    int m0   = mblk * 128;
    int tid  = threadIdx.x;

    if (tid < 128) s_src[tid] = g_gidx[b * L_ + m0 + tid];

    for (int i = tid; i < 128 * NF_; i += 256) {
        int m = i / NF_, c = i % NF_;
        Fs[m * ESTR + c] = feat[((size_t)(b * L_ + m0 + m)) * NF_ + c];
    }
    __syncthreads();
    for (int gg = tid; gg < 32 * ESTR; gg += 256) {
        int f  = gg % ESTR;
        int mq = gg / ESTR;
        float a0 = 0.f, a1 = 0.f, a2 = 0.f, a3 = 0.f;
        if (f < NF_) {
            float bb = __ldg(&enr_b[f]);
            a0 = bb; a1 = bb; a2 = bb; a3 = bb;
            const float* f0 = Fs + (mq * 4 + 0) * ESTR;
            const float* f1 = Fs + (mq * 4 + 1) * ESTR;
            const float* f2 = Fs + (mq * 4 + 2) * ESTR;
            const float* f3 = Fs + (mq * 4 + 3) * ESTR;
            #pragma unroll 4
            for (int k = 0; k < NF_; k++) {
                float w = __ldg(&enr_w[k * NF_ + f]);
                a0 += f0[k] * w; a1 += f1[k] * w;
                a2 += f2[k] * w; a3 += f3[k] * w;
            }
            a0 = fmaxf(a0, 0.f); a1 = fmaxf(a1, 0.f);
            a2 = fmaxf(a2, 0.f); a3 = fmaxf(a3, 0.f);
        }
        E[(mq * 4 + 0) * ESTR + f] = a0;
        E[(mq * 4 + 1) * ESTR + f] = a1;
        E[(mq * 4 + 2) * ESTR + f] = a2;
        E[(mq * 4 + 3) * ESTR + f] = a3;
    }
    __syncthreads();

    size_t tile = (size_t)(b * 4 + mblk);
    uint32_t* oh = g_Xhi + tile * KTILES * 1024;
    uint32_t* ol = g_Xlo + tile * KTILES * 1024;
    bool skip = (m0 >= g_nvalid[b]);     // whole tile zero in seq region

    if (!skip) {
        // seq region, coalesced float4: 128 rows x 192 float4 (kt 0..47)
        for (int idx = tid; idx < 128 * 192; idx += 256) {
            int m = idx / 192, f4 = idx % 192;
            int s = s_src[m];
            float4 v = make_float4(0.f, 0.f, 0.f, 0.f);
            if (s >= 0)
                v = *(const float4*)(seq + ((size_t)(b * L_ + s)) * D_ + f4 * 4);
            int kt = f4 >> 2, jj = (f4 & 3) * 2;
            uint32_t lo0, hi0 = pack_split(v.x, v.y, lo0);
            uint32_t lo1, hi1 = pack_split(v.z, v.w, lo1);
            int base = kt * 1024 + m * 8;
            oh[base + permf(jj)]     = hi0; oh[base + permf(jj + 1)] = hi1;
            ol[base + permf(jj)]     = lo0; ol[base + permf(jj + 1)] = lo1;
        }
    }
    // enrichment region: kt 48..54 (cols 0..111, >=104 zero)
    for (int idx = tid; idx < 128 * 28; idx += 256) {
        int m = idx / 28, f4 = idx % 28;
        int col = f4 * 4;                 // 0..108
        float4 v = make_float4(0.f, 0.f, 0.f, 0.f);
        if (col < ESTR)
            v = *(const float4*)(E + m * ESTR + col);
        int kt = 48 + (col >> 4);
        int jj = (col & 15) >> 1;
        uint32_t lo0, hi0 = pack_split(v.x, v.y, lo0);
        uint32_t lo1, hi1 = pack_split(v.z, v.w, lo1);
        int base = kt * 1024 + m * 8;
        oh[base + permf(jj)]     = hi0; oh[base + permf(jj + 1)] = hi1;
        ol[base + permf(jj)]     = lo0; ol[base + permf(jj + 1)] = lo1;
    }
    // kt 55: zero pad (read by gemm in pair (54,55))
    for (int idx = tid; idx < 1024; idx += 256) {
        oh[55 * 1024 + idx] = 0u;
        ol[55 * 1024 + idx] = 0u;
    }
}

// ---------------------------------------------------------------------------
// Kernel 5: GEMM, one CTA per (tile, nt). 2-ktile stages, 3-deep cp.async,
// LDS.64 fragment loads. Warp (wy,wx): rows wy*64..+64, cols wx*32..+32.
// ---------------------------------------------------------------------------
__global__ __launch_bounds__(256, 2)
void gemm_kernel(const float* __restrict__ b1,
                 const float* __restrict__ w2)
{
    extern __shared__ uint32_t smw[];            // NSTG x 8192 words
    __shared__ float s_tagp[4][128][3];

    int nt   = blockIdx.x;                       // 0..5
    int tile = blockIdx.y;                       // 0..255
    int b    = tile >> 2, mblk = tile & 3;
    int n0   = nt * 128;
    int tid  = threadIdx.x;
    int warp = tid >> 5, lane = tid & 31;
    int wy = warp >> 2, wx = warp & 3;
    int g  = lane >> 2, t4 = lane & 3;

    int kstart = (mblk * 128 >= g_nvalid[b]) ? KSKIP : 0;
    int npair  = (KTILES - kstart) >> 1;         // 28 or 4

    for (int i = tid; i < 4 * 128 * 3; i += 256)
        (&s_tagp[0][0][0])[i] = 0.f;

    const uint32_t* XH = g_Xhi + (size_t)tile * KTILES * 1024;
    const uint32_t* XL = g_Xlo + (size_t)tile * KTILES * 1024;

    uint32_t smem_base = (uint32_t)__cvta_generic_to_shared(smw);

    #define FILL(iv) do {                                                        \
        int _kt0 = kstart + 2 * (iv);                                            \
        uint32_t _sb = smem_base + (uint32_t)(((iv) % NSTG) * STGB);             \
        _Pragma("unroll")                                                        \
        for (int _s = 0; _s < 2; _s++) {                                         \
            int _kt = _kt0 + _s;                                                 \
            uint32_t _d = _sb + (uint32_t)(_s * 16384) + (uint32_t)(tid * 16);   \
            cpa16(_d,         XH + _kt * 1024 + tid * 4);                        \
            cpa16(_d + 4096,  XL + _kt * 1024 + tid * 4);                        \
            cpa16(_d + 8192,  g_Whi + ((size_t)_kt * WAIST_ + n0) * 8 + tid * 4);\
            cpa16(_d + 12288, g_Wlo + ((size_t)_kt * WAIST_ + n0) * 8 + tid * 4);\
        }                                                                        \
        asm volatile("cp.async.commit_group;\n" ::: "memory");                   \
    } while (0)

    float acc[4][4][4];
    #pragma unroll
    for (int mt = 0; mt < 4; mt++)
        #pragma unroll
        for (int nn = 0; nn < 4; nn++)
            #pragma unroll
            for (int q = 0; q < 4; q++) acc[mt][nn][q] = 0.f;

    FILL(0); FILL(1);

    for (int i = 0; i < npair; i++) {
        if (i == npair - 1)
            asm volatile("cp.async.wait_group 0;\n" ::: "memory");
        else
            asm volatile("cp.async.wait_group 1;\n" ::: "memory");
        __syncthreads();                 // stage i ready; stage i-1 reads done
        if (i + 2 < npair) FILL(i + 2);

        uint32_t* stage = smw + (i % NSTG) * STGWRD;
        #pragma unroll
        for (int sub = 0; sub < 2; sub++) {
            const uint2* Ah64 = (const uint2*)(stage + sub * 4096);
            const uint2* Al64 = (const uint2*)(stage + sub * 4096 + 1024);
            const uint2* Bh64 = (const uint2*)(stage + sub * 4096 + 2048);
            const uint2* Bl64 = (const uint2*)(stage + sub * 4096 + 3072);

            uint32_t Bh[4][2], Bl[4][2];
            #pragma unroll
            for (int nn = 0; nn < 4; nn++) {
                int nb = wx * 32 + nn * 8 + g;
                uint2 h = Bh64[nb * 4 + t4];
                uint2 l = Bl64[nb * 4 + t4];
                Bh[nn][0] = h.x; Bh[nn][1] = h.y;
                Bl[nn][0] = l.x; Bl[nn][1] = l.y;
            }
            #pragma unroll
            for (int mt = 0; mt < 4; mt++) {
                int rm = wy * 64 + mt * 16 + g;
                uint2 ah0 = Ah64[rm * 4 + t4];
                uint2 ah1 = Ah64[(rm + 8) * 4 + t4];
                uint2 al0 = Al64[rm * 4 + t4];
                uint2 al1 = Al64[(rm + 8) * 4 + t4];
                uint32_t Ah[4] = {ah0.x, ah1.x, ah0.y, ah1.y};
                uint32_t Al[4] = {al0.x, al1.x, al0.y, al1.y};
                #pragma unroll
                for (int nn = 0; nn < 4; nn++) {
                    mma_bf16(acc[mt][nn], Ah, Bl[nn]);   // small terms first
                    mma_bf16(acc[mt][nn], Al, Bh[nn]);
                    mma_bf16(acc[mt][nn], Ah, Bh[nn]);
                }
            }
        }
    }

    // epilogue: bias + relu + tag partials for this nt
    #pragma unroll
    for (int mt = 0; mt < 4; mt++) {
        float tg0[3] = {0.f, 0.f, 0.f};
        float tg1[3] = {0.f, 0.f, 0.f};
        #pragma unroll
        for (int nn = 0; nn < 4; nn++) {
            #pragma unroll
            for (int cc = 0; cc < 2; cc++) {
                int n = n0 + wx * 32 + nn * 8 + 2 * t4 + cc;
                float bias = __ldg(&b1[n]);
                float w20 = __ldg(&w2[n * 3 + 0]);
                float w21 = __ldg(&w2[n * 3 + 1]);
                float w22 = __ldg(&w2[n * 3 + 2]);
                float h0 = fmaxf(acc[mt][nn][cc]     + bias, 0.f);
                float h1 = fmaxf(acc[mt][nn][cc + 2] + bias, 0.f);
                tg0[0] += h0 * w20; tg0[1] += h0 * w21; tg0[2] += h0 * w22;
                tg1[0] += h1 * w20; tg1[1] += h1 * w21; tg1[2] += h1 * w22;
            }
        }
        #pragma unroll
        for (int t3 = 0; t3 < 3; t3++) {
            tg0[t3] += __shfl_xor_sync(0xffffffffu, tg0[t3], 1);
            tg0[t3] += __shfl_xor_sync(0xffffffffu, tg0[t3], 2);
            tg1[t3] += __shfl_xor_sync(0xffffffffu, tg1[t3], 1);
            tg1[t3] += __shfl_xor_sync(0xffffffffu, tg1[t3], 2);
        }
        if (t4 == 0) {
            int r0 = wy * 64 + mt * 16 + g;
            #pragma unroll
            for (int t3 = 0; t3 < 3; t3++) {
                s_tagp[wx][r0][t3]     = tg0[t3];
                s_tagp[wx][r0 + 8][t3] = tg1[t3];
            }
        }
    }
    __syncthreads();
    // fixed-order wx sum -> global partials for (tile, nt)
    float* dst = g_tagp + (size_t)(tile * NNT + nt) * 384;
    for (int i = tid; i < 384; i += 256) {
        int m = i / 3, t = i % 3;
        dst[i] = s_tagp[0][m][t] + s_tagp[1][m][t]
               + s_tagp[2][m][t] + s_tagp[3][m][t];
    }
    #undef FILL
}

// ---------------------------------------------------------------------------
// Kernel 6: sum nt partials (fixed order) + b2 -> tag_logits
// ---------------------------------------------------------------------------
__global__ void tagred_kernel(const float* __restrict__ b2,
                              float* __restrict__ out)
{
    int tile = blockIdx.x;
    int i = threadIdx.x;                 // 384
    int b = tile >> 2, mblk = tile & 3;
    int m = i / 3, t = i % 3;
    float v = __ldg(&b2[t]);
    #pragma unroll
    for (int nt = 0; nt < NNT; nt++)
        v += g_tagp[(size_t)(tile * NNT + nt) * 384 + i];
    out[128 + ((size_t)(b * L_ + mblk * 128 + m)) * 3 + t] = v;
}

// ---------------------------------------------------------------------------
extern "C" void kernel_launch(void* const* d_in, const int* in_sizes, int n_in,
                              void* d_out, int out_size)
{
    const float* seq   = (const float*)d_in[0];
    const float* feat  = (const float*)d_in[1];
    const int*   valid = (const int*)  d_in[2];
    const float* enr_w = (const float*)d_in[3];
    const float* enr_b = (const float*)d_in[4];
    const float* w1    = (const float*)d_in[5];
    const float* b1    = (const float*)d_in[6];
    const float* w2    = (const float*)d_in[7];
    const float* b2    = (const float*)d_in[8];
    const float* cls_w = (const float*)d_in[9];
    const float* cls_b = (const float*)d_in[10];
    float* out = (float*)d_out;

    const int smem_prep = 2 * 128 * ESTR * (int)sizeof(float);   // 106,496 B
    const int smem_gemm = NSTG * STGB;                           // 98,304 B
    cudaFuncSetAttribute(prepx_kernel, cudaFuncAttributeMaxDynamicSharedMemorySize, smem_prep);
    cudaFuncSetAttribute(gemm_kernel,  cudaFuncAttributeMaxDynamicSharedMemorySize, smem_gemm);

    compact_kernel<<<B_, L_>>>(valid);
    prepw_kernel<<<dim3(8, KTILES), WAIST_>>>(w1);
    prepx_kernel<<<dim3(4, B_), 256, smem_prep>>>(seq, feat, enr_w, enr_b);
    gemm_kernel<<<dim3(NNT, 256), 256, smem_gemm>>>(b1, w2);
    tagred_kernel<<<256, 384>>>(b2, out);
    cls_kernel<<<B_, 256>>>(seq, cls_w, cls_b, out);
}